// round 10
// baseline (speedup 1.0000x reference)
#include <cuda_runtime.h>
#include <math.h>

// ---------------- problem constants ----------------
#define IN_CH   512
#define OUT_CH  512
#define KK      9
#define STYLE_DIM 512
#define B_SZ    8
#define HW      64
#define NPIX    4096              // 64*64
#define CONV_SCALE (1.0f / 67.8822509939086f)   // 1/sqrt(512*9)
#define MOD_SCALE  (1.0f / 22.627416997969522f) // 1/sqrt(512)
#define EPSV 1e-8f

// ---------------- device scratch (no allocs allowed) ----------------
__device__ float g_w5[IN_CH * KK * OUT_CH];   // layout [i][t][o]  (o contiguous)
__device__ float g_W2t[IN_CH * OUT_CH];       // layout [i][o]     (o contiguous)
__device__ float g_sc[B_SZ * IN_CH];          // CONV_SCALE * s[b,i]
__device__ float g_demod[B_SZ * OUT_CH];

// ---------------- f32x2 helpers (sm_103a packed fp32) ----------------
__device__ __forceinline__ unsigned long long pk2(float a, float b) {
    unsigned long long r;
    asm("mov.b64 %0, {%1,%2};" : "=l"(r) : "f"(a), "f"(b));
    return r;
}
__device__ __forceinline__ void unpk2(unsigned long long v, float& lo, float& hi) {
    asm("mov.b64 {%0,%1}, %2;" : "=f"(lo), "=f"(hi) : "l"(v));
}
__device__ __forceinline__ void fma2(unsigned long long& d, unsigned long long a,
                                     unsigned long long b) {
    asm("fma.rn.f32x2 %0, %1, %2, %0;" : "+l"(d) : "l"(a), "l"(b));
}

// ======================================================================
// Kernel 1: w5[o,i,t] = weight + relu(A @ relu(B @ B_inst)); also W2[o,i]
// ======================================================================
__global__ __launch_bounds__(256) void prep_w5_kernel(
    const float* __restrict__ weight,     // [1,512,512,3,3]
    const float* __restrict__ llB,        // [512,4]
    const float* __restrict__ llBinst,    // [4,4,9]
    const float* __restrict__ llA)        // [512,4]
{
    const int o = blockIdx.x;
    const int tid = threadIdx.x;
    __shared__ float Bo[4];
    __shared__ float Bm[4][9];

    if (tid < 4) Bo[tid] = llB[o * 4 + tid];
    __syncthreads();
    if (tid < 36) {
        int b_ = tid / 9, t = tid - b_ * 9;
        float acc = 0.f;
#pragma unroll
        for (int r = 0; r < 4; r++) acc += Bo[r] * llBinst[(b_ * 4 + r) * 9 + t];
        Bm[b_][t] = fmaxf(acc, 0.f);
    }
    __syncthreads();

    for (int i = tid; i < IN_CH; i += 256) {
        float A0 = llA[i * 4 + 0], A1 = llA[i * 4 + 1];
        float A2 = llA[i * 4 + 2], A3 = llA[i * 4 + 3];
        float w2sum = 0.f;
#pragma unroll
        for (int t = 0; t < 9; t++) {
            float add = fmaxf(A0 * Bm[0][t] + A1 * Bm[1][t] + A2 * Bm[2][t] + A3 * Bm[3][t], 0.f);
            float w = weight[(o * IN_CH + i) * 9 + t] + add;
            g_w5[(i * 9 + t) * OUT_CH + o] = w;
            w2sum += w * w;
        }
        g_W2t[i * OUT_CH + o] = w2sum;
    }
}

// ======================================================================
// Kernel 2: sc[b,i] = CONV_SCALE * (MOD_SCALE * style @ w_fc.T + b_fc)
// grid 64: (b, i-chunk of 64); 512 threads
// ======================================================================
__global__ __launch_bounds__(512) void prep_s_kernel(
    const float* __restrict__ style,    // [8,512]
    const float* __restrict__ modW,     // [512,512]
    const float* __restrict__ modB,     // [512]
    const float* __restrict__ fcA,      // [512,4]
    const float* __restrict__ fcB,      // [512,4]
    const float* __restrict__ fcBias)   // [512]
{
    const int b  = blockIdx.x >> 3;
    const int i0 = (blockIdx.x & 7) << 6;
    const int tid = threadIdx.x;
    __shared__ float sty[STYLE_DIM];
    sty[tid] = style[b * STYLE_DIM + tid];
    __syncthreads();

    const int warp = tid >> 5, lane = tid & 31;
    for (int ii = warp; ii < 64; ii += 16) {
        const int i = i0 + ii;
        float4 fb = *(const float4*)&fcB[i * 4];
        float acc = 0.f;
        for (int j = lane; j < STYLE_DIM; j += 32) {
            float4 fa = *(const float4*)&fcA[j * 4];
            float wfc = modW[i * STYLE_DIM + j] +
                        (fb.x * fa.x + fb.y * fa.y + fb.z * fa.z + fb.w * fa.w);
            acc += sty[j] * wfc;
        }
#pragma unroll
        for (int off = 16; off; off >>= 1) acc += __shfl_xor_sync(0xFFFFFFFFu, acc, off);
        if (lane == 0) {
            float s = acc * MOD_SCALE + modB[i] + fcBias[i];
            g_sc[b * IN_CH + i] = s * CONV_SCALE;
        }
    }
}

// ======================================================================
// Kernel 3: demod[b,o] = rsqrt(sum_i sc[b,i]^2 * W2[o,i] + eps)
// ======================================================================
__global__ __launch_bounds__(256) void prep_demod_kernel()
{
    const int id = blockIdx.x * 256 + threadIdx.x;
    const int b = id >> 9, o = id & 511;
    const float* scp = &g_sc[b * IN_CH];
    float acc = 0.f;
#pragma unroll 8
    for (int i = 0; i < IN_CH; i++) {
        float sv = scp[i];
        acc = fmaf(sv * sv, g_W2t[i * OUT_CH + o], acc);
    }
    g_demod[b * OUT_CH + o] = rsqrtf(acc + EPSV);
}

// ======================================================================
// Kernel 4: main conv (hybrid of R5 input path + u64 weights + kw-hoist).
//   out[b,o,y,x] = demod[b,o] * sum_{i,t} w5[o,i,t] * sc[b,i] * in[...]
// Block: (b, 64 o-channels, 2 output rows x 64 wide). 256 threads, ICB=8.
//   ty = tid/16 -> o = o0 + 4*ty..+3 ; tx = tid%16 -> px {tx,tx+16,tx+32,tx+48}
// smem: sWP[ic][t][o'] = (w,w) u64  -> 2x LDS.128 broadcast per (ic,t)
//       sIn[ic][row][x+1] scaled fp32 (single copy, no replication)
// Inner loop per (ic,kw): 8 scalar LDS (pairs pack free via reg pairing),
// then 3 kh x (2 LDS.128 + 16 FFMA2).
// ======================================================================
#define ICB 8
__global__ __launch_bounds__(256, 3) void conv_kernel(
    const float* __restrict__ input,   // [8,512,64,64]
    float* __restrict__ out)           // [8,512,64,64]
{
    const int b  = blockIdx.z;
    const int o0 = blockIdx.y << 6;
    const int y0 = blockIdx.x << 1;
    const int tid = threadIdx.x;
    const int tx = tid & 15;
    const int ty = tid >> 4;

    __shared__ unsigned long long sWP[ICB][9][64];   // 36864 B
    __shared__ float sIn[ICB][4][66];                // 8448 B
    __shared__ float sSc[IN_CH];                     // 2048 B  -> 47360 total

    unsigned long long acc[4][2][2];
#pragma unroll
    for (int a = 0; a < 4; a++)
#pragma unroll
        for (int r = 0; r < 2; r++) { acc[a][r][0] = 0ull; acc[a][r][1] = 0ull; }

    const float* inB = input + (size_t)b * IN_CH * NPIX;
    sSc[tid]       = g_sc[b * IN_CH + tid];
    sSc[tid + 256] = g_sc[b * IN_CH + tid + 256];

#pragma unroll 1
    for (int ic0 = 0; ic0 < IN_CH; ic0 += ICB) {
        __syncthreads();
        // ---- input tile: ICB*4*66 = 2112 floats, single copy, coalesced ----
#pragma unroll
        for (int l = 0; l < 9; l++) {
            int idx = tid + l * 256;
            if (idx < ICB * 4 * 66) {
                int ic  = idx / 264;
                int rem = idx - ic * 264;
                int row = rem / 66;
                int col = rem - row * 66;
                int y = y0 - 1 + row;
                int x = col - 1;
                float v = 0.f;
                if ((unsigned)y < 64u && (unsigned)x < 64u)
                    v = inB[(ic0 + ic) * NPIX + y * 64 + x] * sSc[ic0 + ic];
                sIn[ic][row][col] = v;
            }
        }
        // ---- weights pre-duplicated: ICB*9*64 = 4608 u64, 9 per thread ----
#pragma unroll
        for (int l = 0; l < 9; l++) {
            int e = tid + 256 * l;
            int op   = e & 63;
            int rest = e >> 6;          // 0..71 -> wait, 4608/64=72 groups; 9*256/64=36?? 
            // 4608 u64 total / 256 thr = 18 per thread?  No: ICB*9*64 = 8*9*64 = 4608.
            // Handled below with 18 iterations instead.
            (void)op; (void)rest;
            break;
        }
        // correct weight load: 4608 u64, 18 per thread, coalesced over o
#pragma unroll
        for (int l = 0; l < 18; l++) {
            int e = tid + 256 * l;
            int op   = e & 63;
            int rest = e >> 6;          // 0..71
            int t  = rest % 9;
            int ic = rest / 9;
            float w = g_w5[(ic0 + ic) * (9 * OUT_CH) + t * OUT_CH + o0 + op];
            sWP[ic][t][op] = pk2(w, w);
        }
        __syncthreads();

        // ---- compute ----
#pragma unroll 2
        for (int ic = 0; ic < ICB; ic++) {
#pragma unroll
            for (int kw = 0; kw < 3; kw++) {
                // hoist: 4 halo rows, 2 pixel-pairs each, shared by 3 kh taps
                unsigned long long p[4][2];
#pragma unroll
                for (int row = 0; row < 4; row++) {
                    const float* rp = &sIn[ic][row][tx + kw];
                    p[row][0] = pk2(rp[0],  rp[16]);
                    p[row][1] = pk2(rp[32], rp[48]);
                }
#pragma unroll
                for (int kh = 0; kh < 3; kh++) {
                    const int t = kh * 3 + kw;
                    ulonglong2 wa = *(const ulonglong2*)&sWP[ic][t][ty << 2];
                    ulonglong2 wb = *(const ulonglong2*)&sWP[ic][t][(ty << 2) + 2];
#pragma unroll
                    for (int r = 0; r < 2; r++) {
                        fma2(acc[0][r][0], wa.x, p[r + kh][0]);
                        fma2(acc[0][r][1], wa.x, p[r + kh][1]);
                        fma2(acc[1][r][0], wa.y, p[r + kh][0]);
                        fma2(acc[1][r][1], wa.y, p[r + kh][1]);
                        fma2(acc[2][r][0], wb.x, p[r + kh][0]);
                        fma2(acc[2][r][1], wb.x, p[r + kh][1]);
                        fma2(acc[3][r][0], wb.y, p[r + kh][0]);
                        fma2(acc[3][r][1], wb.y, p[r + kh][1]);
                    }
                }
            }
        }
    }

    // ---- epilogue: apply demod, store (pairs are stride-16 pixels) ----
#pragma unroll
    for (int uo = 0; uo < 4; uo++) {
        const int o = o0 + (ty << 2) + uo;
        const float dm = g_demod[b * OUT_CH + o];
#pragma unroll
        for (int r = 0; r < 2; r++) {
            float* op = out + (((size_t)b * OUT_CH + o) * 64 + (y0 + r)) * 64 + tx;
#pragma unroll
            for (int pi = 0; pi < 2; pi++) {
                float lo, hi;
                unpk2(acc[uo][r][pi], lo, hi);
                op[(2 * pi) * 16]     = lo * dm;
                op[(2 * pi + 1) * 16] = hi * dm;
            }
        }
    }
}

// ======================================================================
extern "C" void kernel_launch(void* const* d_in, const int* in_sizes, int n_in,
                              void* d_out, int out_size)
{
    const float* input   = (const float*)d_in[0];
    const float* style   = (const float*)d_in[1];
    const float* weight  = (const float*)d_in[2];
    const float* llB     = (const float*)d_in[3];
    const float* llBinst = (const float*)d_in[4];
    const float* llA     = (const float*)d_in[5];
    const float* modW    = (const float*)d_in[6];
    const float* modB    = (const float*)d_in[7];
    const float* fcA     = (const float*)d_in[8];
    const float* fcB     = (const float*)d_in[9];
    const float* fcBias  = (const float*)d_in[10];
    float* out = (float*)d_out;

    prep_w5_kernel<<<512, 256>>>(weight, llB, llBinst, llA);
    prep_s_kernel<<<64, 512>>>(style, modW, modB, fcA, fcB, fcBias);
    prep_demod_kernel<<<16, 256>>>();
    conv_kernel<<<dim3(32, 8, 8), 256>>>(input, out);
}

// round 13
// speedup vs baseline: 2.6178x; 2.6178x over previous
#include <cuda_runtime.h>
#include <cstdint>
#include <math.h>

// ---------------- problem constants ----------------
#define IN_CH   512
#define OUT_CH  512
#define STYLE_DIM 512
#define B_SZ    8
#define NPIX    4096
#define CONV_SCALE (1.0f / 67.8822509939086f)   // 1/sqrt(512*9)
#define MOD_SCALE  (1.0f / 22.627416997969522f) // 1/sqrt(512)
#define EPSV 1e-8f

// ---------------- device scratch (no allocs allowed) ----------------
// Xs[b][row 0..65][x 0..63][i] : y-padded, sc-scaled input, tf32-rounded fp32
__device__ __align__(16) float g_Xs[(size_t)B_SZ * 66 * 64 * IN_CH];
// Wt[t][o][i] tf32-rounded fp32 (K-major: i contiguous)
__device__ __align__(16) float g_Wt[9 * OUT_CH * IN_CH];
__device__ float g_W2t[IN_CH * OUT_CH];   // [i][o]
__device__ float g_sc[B_SZ * IN_CH];      // CONV_SCALE * s[b,i]
__device__ float g_demod[B_SZ * OUT_CH];

// ---------------- PTX helpers (plain-target: sm_80+ features only) ----
__device__ __forceinline__ uint32_t s2u(const void* p) {
    uint32_t a;
    asm("{ .reg .u64 t; cvta.to.shared.u64 t, %1; cvt.u32.u64 %0, t; }" : "=r"(a) : "l"(p));
    return a;
}
__device__ __forceinline__ float to_tf32(float v) {
    uint32_t t;
    asm("cvt.rna.tf32.f32 %0, %1;" : "=r"(t) : "f"(v));
    return __uint_as_float(t);
}
__device__ __forceinline__ void cp16(uint32_t d, const void* s) {
    asm volatile("cp.async.cg.shared.global [%0], [%1], 16;" :: "r"(d), "l"(s));
}
__device__ __forceinline__ void cp16z(uint32_t d, const void* s, uint32_t sz) {
    asm volatile("cp.async.cg.shared.global [%0], [%1], 16, %2;" :: "r"(d), "l"(s), "r"(sz));
}
__device__ __forceinline__ void ldsm4(uint32_t* r, uint32_t a) {
    asm volatile("ldmatrix.sync.aligned.m8n8.x4.shared.b16 {%0,%1,%2,%3}, [%4];"
        : "=r"(r[0]), "=r"(r[1]), "=r"(r[2]), "=r"(r[3]) : "r"(a));
}
__device__ __forceinline__ void mma8(float* d, const uint32_t* a, uint32_t b0, uint32_t b1) {
    asm volatile("mma.sync.aligned.m16n8k8.row.col.f32.tf32.tf32.f32 "
        "{%0,%1,%2,%3},{%4,%5,%6,%7},{%8,%9},{%0,%1,%2,%3};"
        : "+f"(d[0]), "+f"(d[1]), "+f"(d[2]), "+f"(d[3])
        : "r"(a[0]), "r"(a[1]), "r"(a[2]), "r"(a[3]), "r"(b0), "r"(b1));
}

// ======================================================================
// Kernel 1: w5 = weight + relu(A @ relu(B @ B_inst)) -> g_Wt tf32 [t][o][i]
// and W2[i][o] = sum_t w5^2 (exact fp32).   grid 512 (per o), 256 thr
// ======================================================================
__global__ __launch_bounds__(256) void prep_w5_kernel(
    const float* __restrict__ weight, const float* __restrict__ llB,
    const float* __restrict__ llBinst, const float* __restrict__ llA)
{
    const int o = blockIdx.x;
    const int tid = threadIdx.x;
    __shared__ float Bo[4];
    __shared__ float Bm[4][9];

    if (tid < 4) Bo[tid] = llB[o * 4 + tid];
    __syncthreads();
    if (tid < 36) {
        int b_ = tid / 9, t = tid - b_ * 9;
        float acc = 0.f;
#pragma unroll
        for (int r = 0; r < 4; r++) acc += Bo[r] * llBinst[(b_ * 4 + r) * 9 + t];
        Bm[b_][t] = fmaxf(acc, 0.f);
    }
    __syncthreads();

    for (int i = tid; i < IN_CH; i += 256) {
        float A0 = llA[i * 4 + 0], A1 = llA[i * 4 + 1];
        float A2 = llA[i * 4 + 2], A3 = llA[i * 4 + 3];
        float w2sum = 0.f;
#pragma unroll
        for (int t = 0; t < 9; t++) {
            float add = fmaxf(A0 * Bm[0][t] + A1 * Bm[1][t] + A2 * Bm[2][t] + A3 * Bm[3][t], 0.f);
            float w = weight[(o * IN_CH + i) * 9 + t] + add;
            g_Wt[((size_t)t * OUT_CH + o) * IN_CH + i] = to_tf32(w);
            w2sum += w * w;
        }
        g_W2t[i * OUT_CH + o] = w2sum;
    }
}

// ======================================================================
// Kernel 2: sc[b,i] = CONV_SCALE * (MOD_SCALE * style @ w_fc.T + b_fc)
// ======================================================================
__global__ __launch_bounds__(512) void prep_s_kernel(
    const float* __restrict__ style, const float* __restrict__ modW,
    const float* __restrict__ modB, const float* __restrict__ fcA,
    const float* __restrict__ fcB, const float* __restrict__ fcBias)
{
    const int b  = blockIdx.x >> 3;
    const int i0 = (blockIdx.x & 7) << 6;
    const int tid = threadIdx.x;
    __shared__ float sty[STYLE_DIM];
    sty[tid] = style[b * STYLE_DIM + tid];
    __syncthreads();

    const int warp = tid >> 5, lane = tid & 31;
    for (int ii = warp; ii < 64; ii += 16) {
        const int i = i0 + ii;
        float4 fb = *(const float4*)&fcB[i * 4];
        float acc = 0.f;
        for (int j = lane; j < STYLE_DIM; j += 32) {
            float4 fa = *(const float4*)&fcA[j * 4];
            float wfc = modW[i * STYLE_DIM + j] +
                        (fb.x * fa.x + fb.y * fa.y + fb.z * fa.z + fb.w * fa.w);
            acc += sty[j] * wfc;
        }
#pragma unroll
        for (int off = 16; off; off >>= 1) acc += __shfl_xor_sync(0xFFFFFFFFu, acc, off);
        if (lane == 0) {
            float s = acc * MOD_SCALE + modB[i] + fcBias[i];
            g_sc[b * IN_CH + i] = s * CONV_SCALE;
        }
    }
}

// ======================================================================
// Kernel 3: demod[b,o] = rsqrt(sum_i sc^2 * W2[i][o] + eps)  (exact fp32)
// ======================================================================
__global__ __launch_bounds__(256) void prep_demod_kernel()
{
    const int id = blockIdx.x * 256 + threadIdx.x;
    const int b = id >> 9, o = id & 511;
    const float* scp = &g_sc[b * IN_CH];
    float acc = 0.f;
#pragma unroll 8
    for (int i = 0; i < IN_CH; i++) {
        float sv = scp[i];
        acc = fmaf(sv * sv, g_W2t[i * OUT_CH + o], acc);
    }
    g_demod[b * OUT_CH + o] = rsqrtf(acc + EPSV);
}

// ======================================================================
// Kernel 4: build Xs[b][row][x][i] = tf32( in[b][i][row-1][x] * sc[b,i] )
// rows 0 and 65 are zero padding. grid 528 = (b, row), 256 threads.
// ======================================================================
__global__ __launch_bounds__(256) void prep_xs_kernel(const float* __restrict__ input)
{
    const int b   = blockIdx.x / 66;
    const int row = blockIdx.x - b * 66;
    const int y   = row - 1;
    const bool valid = (unsigned)y < 64u;
    const int tid = threadIdx.x;

    __shared__ float tile[32][65];
    __shared__ float ssc[32];

    for (int i0 = 0; i0 < IN_CH; i0 += 32) {
        __syncthreads();
        if (tid < 32) ssc[tid] = g_sc[b * IN_CH + i0 + tid];
        if (valid) {
#pragma unroll
            for (int p = 0; p < 8; p++) {
                int idx = tid + p * 256;
                int ii = idx >> 6, x = idx & 63;
                tile[ii][x] = input[((size_t)b * IN_CH + i0 + ii) * NPIX + y * 64 + x];
            }
        }
        __syncthreads();
        size_t obase = (((size_t)b * 66 + row) * 64) * IN_CH;
#pragma unroll
        for (int p = 0; p < 4; p++) {
            int idx = tid + p * 256;      // 0..1023
            int x  = idx >> 4;            // 0..63
            int ip = (idx & 15) * 2;      // even i_local
            float s0 = 0.f, s1 = 0.f;
            if (valid) {
                s0 = to_tf32(tile[ip][x]     * ssc[ip]);
                s1 = to_tf32(tile[ip + 1][x] * ssc[ip + 1]);
            }
            *(float2*)&g_Xs[obase + (size_t)x * IN_CH + i0 + ip] = make_float2(s0, s1);
        }
    }
}

// ======================================================================
// Kernel 5: tf32 mma.sync implicit-GEMM conv.
// CTA: M=256 px (4 y-rows) x N=128 o. 8 warps (4x2), warp tile 64x64.
// K loop: 9 taps x 16 chunks of K=32, cp.async double-buffered.
// smem row = 32 f32 = 128B, SW128 swizzle; ldmatrix-b16 trick for tf32.
// grid (16 Mtiles, 4 Ntiles, 8 b) = 512 CTAs, 256 threads, 96KB dyn smem.
// ======================================================================
#define STAGE_BYTES 49152   // A 32768 + B 16384
#define DSMEM_BYTES (2 * STAGE_BYTES)

__global__ __launch_bounds__(256) void conv_tc_kernel(float* __restrict__ out)
{
    extern __shared__ __align__(16) char dyn[];
    __shared__ float sDm[128];

    const int T  = blockIdx.x;            // M tile: output rows 4T..4T+3
    const int o0 = blockIdx.y << 7;       // N tile base (128 o)
    const int b  = blockIdx.z;
    const int tid  = threadIdx.x;
    const int lane = tid & 31;
    const int wid  = tid >> 5;
    const int wm = wid >> 1;              // 0..3  (m warp: 64 px)
    const int wn = wid & 1;               // 0..1  (n warp: 64 o)
    const uint32_t sbase = s2u(dyn);

    if (tid < 128) sDm[tid] = g_demod[b * OUT_CH + o0 + tid];

    // ---- load-side constants ----
    const int g  = tid & 7;               // 16B k-segment (0..7)
    const int r0 = tid >> 3;              // base row; rows r0 + 32j
    const uint32_t lmask = (uint32_t)((r0 & 7) << 4) & 0x70;
    const uint32_t dst0  = (uint32_t)(r0 * 128) + (((uint32_t)g * 16) ^ lmask);

    // ---- compute-side constants ----
    const int rA  = lane & 15;
    const int ghA = lane >> 4;
    const uint32_t maskA = (uint32_t)((rA & 7) << 4) & 0x70;
    const uint32_t offA0 = (uint32_t)((wm * 64 + rA) * 128);
    const int rB  = (lane & 7) | ((lane >> 4) << 3);
    const int ghB = (lane >> 3) & 1;
    const uint32_t maskB = (uint32_t)((rB & 7) << 4) & 0x70;
    const uint32_t offB0 = (uint32_t)((wn * 64 + rB) * 128);

    float acc[4][8][4];
#pragma unroll
    for (int mt = 0; mt < 4; mt++)
#pragma unroll
        for (int nt = 0; nt < 8; nt++)
#pragma unroll
            for (int q = 0; q < 4; q++) acc[mt][nt][q] = 0.f;

    const float* Xb = g_Xs + ((size_t)b * 66) * 64 * IN_CH;

    // chunk loader: it -> (tap, i0); stage in {0,1}
    auto load_chunk = [&](int it, int stage) {
        const int t  = it >> 4;
        const int i0 = (it & 15) << 5;
        const int kh = t / 3;
        const int kw = t - kh * 3;
        const int rowbase = 4 * T + kh;          // padded row of first pixel row
        const uint32_t sA = sbase + stage * STAGE_BYTES;
        const uint32_t sB = sA + 32768;
        // A: 256 rows (pixels) x 32 k
#pragma unroll
        for (int j = 0; j < 8; j++) {
            int px = r0 + 32 * j;
            int x  = px & 63;
            int xs = x + kw - 1;
            int yp = rowbase + (px >> 6);
            uint32_t ok = ((unsigned)xs < 64u) ? 16u : 0u;
            int xsc = ok ? xs : 0;
            const float* src = Xb + ((size_t)yp * 64 + xsc) * IN_CH + i0 + g * 4;
            cp16z(sA + dst0 + j * 4096, src, ok);
        }
        // B: 128 rows (o) x 32 k
        const float* wsrc = g_Wt + ((size_t)t * OUT_CH + o0) * IN_CH + i0 + g * 4;
#pragma unroll
        for (int j = 0; j < 4; j++) {
            cp16(sB + dst0 + j * 4096, wsrc + (size_t)(r0 + 32 * j) * IN_CH);
        }
        asm volatile("cp.async.commit_group;" ::: "memory");
    };

    load_chunk(0, 0);

#pragma unroll 1
    for (int it = 0; it < 144; it++) {
        const int p = it & 1;
        if (it < 143) {
            load_chunk(it + 1, p ^ 1);
            asm volatile("cp.async.wait_group 1;" ::: "memory");
        } else {
            asm volatile("cp.async.wait_group 0;" ::: "memory");
        }
        __syncthreads();

        const uint32_t aA = sbase + p * STAGE_BYTES;
        const uint32_t aB = aA + 32768;
#pragma unroll
        for (int ks = 0; ks < 4; ks++) {
            const uint32_t kpa = ((uint32_t)(ks * 32 + ghA * 16)) ^ maskA;
            const uint32_t kpb = ((uint32_t)(ks * 32 + ghB * 16)) ^ maskB;
            uint32_t af[4][4];
#pragma unroll
            for (int mt = 0; mt < 4; mt++)
                ldsm4(af[mt], aA + offA0 + mt * 2048 + kpa);
            uint32_t bf[4][4];
#pragma unroll
            for (int np = 0; np < 4; np++)
                ldsm4(bf[np], aB + offB0 + np * 2048 + kpb);
#pragma unroll
            for (int mt = 0; mt < 4; mt++) {
#pragma unroll
                for (int np = 0; np < 4; np++) {
                    mma8(acc[mt][2 * np],     af[mt], bf[np][0], bf[np][1]);
                    mma8(acc[mt][2 * np + 1], af[mt], bf[np][2], bf[np][3]);
                }
            }
        }
        __syncthreads();
    }

    // ---- epilogue: y = 4T + wm; x = mt*16 + lane/4 (+8); n = wn*64+nt*8+2*(lane&3) (+1)
    const int y  = 4 * T + wm;
    const int xr = lane >> 2;
#pragma unroll
    for (int mt = 0; mt < 4; mt++) {
        const int x0 = mt * 16 + xr;
#pragma unroll
        for (int nt = 0; nt < 8; nt++) {
            const int n0 = wn * 64 + nt * 8 + 2 * (lane & 3);
            const float dm0 = sDm[n0], dm1 = sDm[n0 + 1];
            float* b0p = out + ((size_t)(b * OUT_CH + o0 + n0)) * NPIX + y * 64;
            float* b1p = b0p + NPIX;
            b0p[x0]     = acc[mt][nt][0] * dm0;
            b1p[x0]     = acc[mt][nt][1] * dm1;
            b0p[x0 + 8] = acc[mt][nt][2] * dm0;
            b1p[x0 + 8] = acc[mt][nt][3] * dm1;
        }
    }
}

// ======================================================================
extern "C" void kernel_launch(void* const* d_in, const int* in_sizes, int n_in,
                              void* d_out, int out_size)
{
    const float* input   = (const float*)d_in[0];
    const float* style   = (const float*)d_in[1];
    const float* weight  = (const float*)d_in[2];
    const float* llB     = (const float*)d_in[3];
    const float* llBinst = (const float*)d_in[4];
    const float* llA     = (const float*)d_in[5];
    const float* modW    = (const float*)d_in[6];
    const float* modB    = (const float*)d_in[7];
    const float* fcA     = (const float*)d_in[8];
    const float* fcB     = (const float*)d_in[9];
    const float* fcBias  = (const float*)d_in[10];
    float* out = (float*)d_out;

    cudaFuncSetAttribute(conv_tc_kernel,
                         cudaFuncAttributeMaxDynamicSharedMemorySize, DSMEM_BYTES);

    prep_w5_kernel<<<512, 256>>>(weight, llB, llBinst, llA);
    prep_s_kernel<<<64, 512>>>(style, modW, modB, fcA, fcB, fcBias);
    prep_demod_kernel<<<16, 256>>>();
    prep_xs_kernel<<<528, 256>>>(input);
    conv_tc_kernel<<<dim3(16, 4, 8), 256, DSMEM_BYTES>>>(out);
}

// round 14
// speedup vs baseline: 6.4381x; 2.4593x over previous
#include <cuda_runtime.h>
#include <cuda_fp16.h>
#include <cstdint>
#include <math.h>

// ---------------- problem constants ----------------
#define IN_CH   512
#define OUT_CH  512
#define STYLE_DIM 512
#define B_SZ    8
#define NPIX    4096
#define CONV_SCALE (1.0f / 67.8822509939086f)   // 1/sqrt(512*9)
#define MOD_SCALE  (1.0f / 22.627416997969522f) // 1/sqrt(512)
#define EPSV 1e-8f

// ---------------- device scratch (no allocs allowed) ----------------
// Xs[b][row 0..65][x 0..63][i] : y-padded, sc-scaled input, fp16
__device__ __align__(16) __half g_Xs[(size_t)B_SZ * 66 * 64 * IN_CH];
// Wt[t][o][i] fp16 (K-major: i contiguous)
__device__ __align__(16) __half g_Wt[9 * OUT_CH * IN_CH];
__device__ float g_W2t[IN_CH * OUT_CH];   // [i][o]
__device__ float g_sc[B_SZ * IN_CH];      // CONV_SCALE * s[b,i]
__device__ float g_demod[B_SZ * OUT_CH];

// ---------------- PTX helpers (plain-target sm_80+ features only) ----
__device__ __forceinline__ uint32_t s2u(const void* p) {
    uint32_t a;
    asm("{ .reg .u64 t; cvta.to.shared.u64 t, %1; cvt.u32.u64 %0, t; }" : "=r"(a) : "l"(p));
    return a;
}
__device__ __forceinline__ void cp16(uint32_t d, const void* s) {
    asm volatile("cp.async.cg.shared.global [%0], [%1], 16;" :: "r"(d), "l"(s));
}
__device__ __forceinline__ void cp16z(uint32_t d, const void* s, uint32_t sz) {
    asm volatile("cp.async.cg.shared.global [%0], [%1], 16, %2;" :: "r"(d), "l"(s), "r"(sz));
}
__device__ __forceinline__ void ldsm4(uint32_t* r, uint32_t a) {
    asm volatile("ldmatrix.sync.aligned.m8n8.x4.shared.b16 {%0,%1,%2,%3}, [%4];"
        : "=r"(r[0]), "=r"(r[1]), "=r"(r[2]), "=r"(r[3]) : "r"(a));
}
// fp16 MMA: m16n8k16, fp32 accum
__device__ __forceinline__ void mma16(float* d, const uint32_t* a, uint32_t b0, uint32_t b1) {
    asm volatile("mma.sync.aligned.m16n8k16.row.col.f32.f16.f16.f32 "
        "{%0,%1,%2,%3},{%4,%5,%6,%7},{%8,%9},{%0,%1,%2,%3};"
        : "+f"(d[0]), "+f"(d[1]), "+f"(d[2]), "+f"(d[3])
        : "r"(a[0]), "r"(a[1]), "r"(a[2]), "r"(a[3]), "r"(b0), "r"(b1));
}

// ======================================================================
// Kernel 1: w5 = weight + relu(A @ relu(B @ B_inst)) -> g_Wt fp16 [t][o][i]
// and W2[i][o] = sum_t w5^2 (exact fp32).   grid 512 (per o), 256 thr
// ======================================================================
__global__ __launch_bounds__(256) void prep_w5_kernel(
    const float* __restrict__ weight, const float* __restrict__ llB,
    const float* __restrict__ llBinst, const float* __restrict__ llA)
{
    const int o = blockIdx.x;
    const int tid = threadIdx.x;
    __shared__ float Bo[4];
    __shared__ float Bm[4][9];

    if (tid < 4) Bo[tid] = llB[o * 4 + tid];
    __syncthreads();
    if (tid < 36) {
        int b_ = tid / 9, t = tid - b_ * 9;
        float acc = 0.f;
#pragma unroll
        for (int r = 0; r < 4; r++) acc += Bo[r] * llBinst[(b_ * 4 + r) * 9 + t];
        Bm[b_][t] = fmaxf(acc, 0.f);
    }
    __syncthreads();

    for (int i = tid; i < IN_CH; i += 256) {
        float A0 = llA[i * 4 + 0], A1 = llA[i * 4 + 1];
        float A2 = llA[i * 4 + 2], A3 = llA[i * 4 + 3];
        float w2sum = 0.f;
#pragma unroll
        for (int t = 0; t < 9; t++) {
            float add = fmaxf(A0 * Bm[0][t] + A1 * Bm[1][t] + A2 * Bm[2][t] + A3 * Bm[3][t], 0.f);
            float w = weight[(o * IN_CH + i) * 9 + t] + add;
            g_Wt[((size_t)t * OUT_CH + o) * IN_CH + i] = __float2half_rn(w);
            w2sum += w * w;
        }
        g_W2t[i * OUT_CH + o] = w2sum;
    }
}

// ======================================================================
// Kernel 2: sc[b,i] = CONV_SCALE * (MOD_SCALE * style @ w_fc.T + b_fc)
// ======================================================================
__global__ __launch_bounds__(512) void prep_s_kernel(
    const float* __restrict__ style, const float* __restrict__ modW,
    const float* __restrict__ modB, const float* __restrict__ fcA,
    const float* __restrict__ fcB, const float* __restrict__ fcBias)
{
    const int b  = blockIdx.x >> 3;
    const int i0 = (blockIdx.x & 7) << 6;
    const int tid = threadIdx.x;
    __shared__ float sty[STYLE_DIM];
    sty[tid] = style[b * STYLE_DIM + tid];
    __syncthreads();

    const int warp = tid >> 5, lane = tid & 31;
    for (int ii = warp; ii < 64; ii += 16) {
        const int i = i0 + ii;
        float4 fb = *(const float4*)&fcB[i * 4];
        float acc = 0.f;
        for (int j = lane; j < STYLE_DIM; j += 32) {
            float4 fa = *(const float4*)&fcA[j * 4];
            float wfc = modW[i * STYLE_DIM + j] +
                        (fb.x * fa.x + fb.y * fa.y + fb.z * fa.z + fb.w * fa.w);
            acc += sty[j] * wfc;
        }
#pragma unroll
        for (int off = 16; off; off >>= 1) acc += __shfl_xor_sync(0xFFFFFFFFu, acc, off);
        if (lane == 0) {
            float s = acc * MOD_SCALE + modB[i] + fcBias[i];
            g_sc[b * IN_CH + i] = s * CONV_SCALE;
        }
    }
}

// ======================================================================
// Kernel 3: demod[b,o] = rsqrt(sum_i sc^2 * W2[i][o] + eps)  (exact fp32)
// ======================================================================
__global__ __launch_bounds__(256) void prep_demod_kernel()
{
    const int id = blockIdx.x * 256 + threadIdx.x;
    const int b = id >> 9, o = id & 511;
    const float* scp = &g_sc[b * IN_CH];
    float acc = 0.f;
#pragma unroll 8
    for (int i = 0; i < IN_CH; i++) {
        float sv = scp[i];
        acc = fmaf(sv * sv, g_W2t[i * OUT_CH + o], acc);
    }
    g_demod[b * OUT_CH + o] = rsqrtf(acc + EPSV);
}

// ======================================================================
// Kernel 4: build Xs[b][row][x][i] = fp16( in[b][i][row-1][x] * sc[b,i] )
// rows 0 and 65 are zero padding. grid 528 = (b, row), 256 threads.
// ======================================================================
__global__ __launch_bounds__(256) void prep_xs_kernel(const float* __restrict__ input)
{
    const int b   = blockIdx.x / 66;
    const int row = blockIdx.x - b * 66;
    const int y   = row - 1;
    const bool valid = (unsigned)y < 64u;
    const int tid = threadIdx.x;

    __shared__ float tile[32][65];
    __shared__ float ssc[32];

    for (int i0 = 0; i0 < IN_CH; i0 += 32) {
        __syncthreads();
        if (tid < 32) ssc[tid] = g_sc[b * IN_CH + i0 + tid];
        if (valid) {
#pragma unroll
            for (int p = 0; p < 8; p++) {
                int idx = tid + p * 256;
                int ii = idx >> 6, x = idx & 63;
                tile[ii][x] = input[((size_t)b * IN_CH + i0 + ii) * NPIX + y * 64 + x];
            }
        }
        __syncthreads();
        size_t obase = (((size_t)b * 66 + row) * 64) * IN_CH;
#pragma unroll
        for (int p = 0; p < 4; p++) {
            int idx = tid + p * 256;      // 0..1023
            int x  = idx >> 4;            // 0..63
            int ip = (idx & 15) * 2;      // even i_local
            float s0 = 0.f, s1 = 0.f;
            if (valid) {
                s0 = tile[ip][x]     * ssc[ip];
                s1 = tile[ip + 1][x] * ssc[ip + 1];
            }
            *(__half2*)&g_Xs[obase + (size_t)x * IN_CH + i0 + ip] =
                __floats2half2_rn(s0, s1);
        }
    }
}

// ======================================================================
// Kernel 5: fp16 mma.sync implicit-GEMM conv.
// CTA: M=256 px (4 y-rows) x N=128 o. 8 warps (4x2), warp tile 64x64.
// K loop: 9 taps x 8 chunks of K=64 halves (row = 128B, SW128 swizzle),
// cp.async double-buffered (2 x 48KB).
// Fragments: ldmatrix.x4 b16, row = lane&15, k-half = lane>>4 (A and B).
// grid (16 Mtiles, 4 Ntiles, 8 b) = 512 CTAs, 256 threads, 96KB dyn smem.
// ======================================================================
#define STAGE_BYTES 49152   // A 32768 + B 16384
#define DSMEM_BYTES (2 * STAGE_BYTES)

__global__ __launch_bounds__(256) void conv_tc_kernel(float* __restrict__ out)
{
    extern __shared__ __align__(16) char dyn[];
    __shared__ float sDm[128];

    const int T  = blockIdx.x;            // M tile: output rows 4T..4T+3
    const int o0 = blockIdx.y << 7;       // N tile base (128 o)
    const int b  = blockIdx.z;
    const int tid  = threadIdx.x;
    const int lane = tid & 31;
    const int wid  = tid >> 5;
    const int wm = wid >> 1;              // 0..3  (m warp: 64 px = y-row wm)
    const int wn = wid & 1;               // 0..1  (n warp: 64 o)
    const uint32_t sbase = s2u(dyn);

    if (tid < 128) sDm[tid] = g_demod[b * OUT_CH + o0 + tid];

    // ---- load-side constants (16B segment = 8 halves) ----
    const int g  = tid & 7;               // k-segment 0..7
    const int r0 = tid >> 3;              // base row; rows r0 + 32j
    const uint32_t dst0 = (uint32_t)(r0 * 128) + (((uint32_t)g * 16) ^ ((uint32_t)(r0 & 7) << 4));

    // ---- compute-side constants ----
    const int rF  = lane & 15;            // fragment row (m for A, n for B)
    const int gh  = lane >> 4;            // k-half (16B)
    const uint32_t maskF = (uint32_t)((rF & 7) << 4);
    const uint32_t offA0 = (uint32_t)((wm * 64 + rF) * 128);
    const uint32_t offB0 = (uint32_t)((wn * 64 + rF) * 128);

    float acc[4][8][4];
#pragma unroll
    for (int mt = 0; mt < 4; mt++)
#pragma unroll
        for (int nt = 0; nt < 8; nt++)
#pragma unroll
            for (int q = 0; q < 4; q++) acc[mt][nt][q] = 0.f;

    const __half* Xb = g_Xs + ((size_t)b * 66) * 64 * IN_CH;

    // chunk loader: it in 0..71 -> (tap = it>>3, i0 = (it&7)*64)
    auto load_chunk = [&](int it, int stage) {
        const int t  = it >> 3;
        const int i0 = (it & 7) << 6;
        const int kh = t / 3;
        const int kw = t - kh * 3;
        const int rowbase = 4 * T + kh;          // padded row of first pixel row
        const uint32_t sA = sbase + stage * STAGE_BYTES;
        const uint32_t sB = sA + 32768;
        // A: 256 rows (pixels) x 64 halves
#pragma unroll
        for (int j = 0; j < 8; j++) {
            int px = r0 + 32 * j;
            int x  = px & 63;
            int xs = x + kw - 1;
            int yp = rowbase + (px >> 6);
            uint32_t ok = ((unsigned)xs < 64u) ? 16u : 0u;
            int xsc = ok ? xs : 0;
            const __half* src = Xb + ((size_t)yp * 64 + xsc) * IN_CH + i0 + g * 8;
            cp16z(sA + dst0 + j * 4096, src, ok);
        }
        // B: 128 rows (o) x 64 halves
        const __half* wsrc = g_Wt + ((size_t)t * OUT_CH + o0) * IN_CH + i0 + g * 8;
#pragma unroll
        for (int j = 0; j < 4; j++) {
            cp16(sB + dst0 + j * 4096, wsrc + (size_t)(r0 + 32 * j) * IN_CH);
        }
        asm volatile("cp.async.commit_group;" ::: "memory");
    };

    load_chunk(0, 0);

#pragma unroll 1
    for (int it = 0; it < 72; it++) {
        const int p = it & 1;
        if (it < 71) {
            load_chunk(it + 1, p ^ 1);
            asm volatile("cp.async.wait_group 1;" ::: "memory");
        } else {
            asm volatile("cp.async.wait_group 0;" ::: "memory");
        }
        __syncthreads();

        const uint32_t aA = sbase + p * STAGE_BYTES;
        const uint32_t aB = aA + 32768;
#pragma unroll
        for (int ks = 0; ks < 4; ks++) {          // 4 k16 groups in K=64
            const uint32_t kcol = ((uint32_t)(ks * 32 + gh * 16)) ^ maskF;
            uint32_t af[4][4];
#pragma unroll
            for (int mt = 0; mt < 4; mt++)
                ldsm4(af[mt], aA + offA0 + mt * 2048 + kcol);
            uint32_t bf[4][4];
#pragma unroll
            for (int np = 0; np < 4; np++)
                ldsm4(bf[np], aB + offB0 + np * 2048 + kcol);
            // bf[np]: {n0-7 klo, n8-15 klo, n0-7 khi, n8-15 khi}
#pragma unroll
            for (int mt = 0; mt < 4; mt++) {
#pragma unroll
                for (int np = 0; np < 4; np++) {
                    mma16(acc[mt][2 * np],     af[mt], bf[np][0], bf[np][2]);
                    mma16(acc[mt][2 * np + 1], af[mt], bf[np][1], bf[np][3]);
                }
            }
        }
        __syncthreads();
    }

    // ---- epilogue: y = 4T + wm; x = mt*16 + lane/4 (+8); n = wn*64+nt*8+2*(lane&3) (+1)
    const int y  = 4 * T + wm;
    const int xr = lane >> 2;
#pragma unroll
    for (int mt = 0; mt < 4; mt++) {
        const int x0 = mt * 16 + xr;
#pragma unroll
        for (int nt = 0; nt < 8; nt++) {
            const int n0 = wn * 64 + nt * 8 + 2 * (lane & 3);
            const float dm0 = sDm[n0], dm1 = sDm[n0 + 1];
            float* b0p = out + ((size_t)(b * OUT_CH + o0 + n0)) * NPIX + y * 64;
            float* b1p = b0p + NPIX;
            b0p[x0]     = acc[mt][nt][0] * dm0;
            b1p[x0]     = acc[mt][nt][1] * dm1;
            b0p[x0 + 8] = acc[mt][nt][2] * dm0;
            b1p[x0 + 8] = acc[mt][nt][3] * dm1;
        }
    }
}

// ======================================================================
extern "C" void kernel_launch(void* const* d_in, const int* in_sizes, int n_in,
                              void* d_out, int out_size)
{
    const float* input   = (const float*)d_in[0];
    const float* style   = (const float*)d_in[1];
    const float* weight  = (const float*)d_in[2];
    const float* llB     = (const float*)d_in[3];
    const float* llBinst = (const float*)d_in[4];
    const float* llA     = (const float*)d_in[5];
    const float* modW    = (const float*)d_in[6];
    const float* modB    = (const float*)d_in[7];
    const float* fcA     = (const float*)d_in[8];
    const float* fcB     = (const float*)d_in[9];
    const float* fcBias  = (const float*)d_in[10];
    float* out = (float*)d_out;

    cudaFuncSetAttribute(conv_tc_kernel,
                         cudaFuncAttributeMaxDynamicSharedMemorySize, DSMEM_BYTES);

    prep_w5_kernel<<<512, 256>>>(weight, llB, llBinst, llA);
    prep_s_kernel<<<64, 512>>>(style, modW, modB, fcA, fcB, fcBias);
    prep_demod_kernel<<<16, 256>>>();
    prep_xs_kernel<<<528, 256>>>(input);
    conv_tc_kernel<<<dim3(16, 4, 8), 256, DSMEM_BYTES>>>(out);
}

// round 15
// speedup vs baseline: 7.6182x; 1.1833x over previous
#include <cuda_runtime.h>
#include <cuda_fp16.h>
#include <cstdint>
#include <math.h>

// ---------------- problem constants ----------------
#define IN_CH   512
#define OUT_CH  512
#define STYLE_DIM 512
#define B_SZ    8
#define NPIX    4096
#define CONV_SCALE (1.0f / 67.8822509939086f)   // 1/sqrt(512*9)
#define MOD_SCALE  (1.0f / 22.627416997969522f) // 1/sqrt(512)
#define EPSV 1e-8f

// ---------------- device scratch (no allocs allowed) ----------------
// Xs[b][row 0..65][x 0..63][i] : y-padded, sc-scaled input, fp16
__device__ __align__(16) __half g_Xs[(size_t)B_SZ * 66 * 64 * IN_CH];
// Wt[t][o][i] fp16 (K-major: i contiguous)
__device__ __align__(16) __half g_Wt[9 * OUT_CH * IN_CH];
__device__ float g_W2t[IN_CH * OUT_CH];   // [i][o]
__device__ float g_sc[B_SZ * IN_CH];      // CONV_SCALE * s[b,i]
__device__ float g_demod[B_SZ * OUT_CH];

// ---------------- PTX helpers (plain-target sm_80+ features only) ----
__device__ __forceinline__ uint32_t s2u(const void* p) {
    uint32_t a;
    asm("{ .reg .u64 t; cvta.to.shared.u64 t, %1; cvt.u32.u64 %0, t; }" : "=r"(a) : "l"(p));
    return a;
}
__device__ __forceinline__ void cp16(uint32_t d, const void* s) {
    asm volatile("cp.async.cg.shared.global [%0], [%1], 16;" :: "r"(d), "l"(s));
}
__device__ __forceinline__ void cp16z(uint32_t d, const void* s, uint32_t sz) {
    asm volatile("cp.async.cg.shared.global [%0], [%1], 16, %2;" :: "r"(d), "l"(s), "r"(sz));
}
__device__ __forceinline__ void ldsm4(uint32_t* r, uint32_t a) {
    asm volatile("ldmatrix.sync.aligned.m8n8.x4.shared.b16 {%0,%1,%2,%3}, [%4];"
        : "=r"(r[0]), "=r"(r[1]), "=r"(r[2]), "=r"(r[3]) : "r"(a));
}
// fp16 MMA: m16n8k16, fp32 accum
__device__ __forceinline__ void mma16(float* d, const uint32_t* a, uint32_t b0, uint32_t b1) {
    asm volatile("mma.sync.aligned.m16n8k16.row.col.f32.f16.f16.f32 "
        "{%0,%1,%2,%3},{%4,%5,%6,%7},{%8,%9},{%0,%1,%2,%3};"
        : "+f"(d[0]), "+f"(d[1]), "+f"(d[2]), "+f"(d[3])
        : "r"(a[0]), "r"(a[1]), "r"(a[2]), "r"(a[3]), "r"(b0), "r"(b1));
}

// ======================================================================
// Kernel 1: w5 = weight + relu(A @ relu(B @ B_inst)) -> g_Wt fp16 [t][o][i]
// and W2[i][o] = sum_t w5^2 (exact fp32).   grid 512 (per o), 256 thr
// ======================================================================
__global__ __launch_bounds__(256) void prep_w5_kernel(
    const float* __restrict__ weight, const float* __restrict__ llB,
    const float* __restrict__ llBinst, const float* __restrict__ llA)
{
    const int o = blockIdx.x;
    const int tid = threadIdx.x;
    __shared__ float Bo[4];
    __shared__ float Bm[4][9];

    if (tid < 4) Bo[tid] = llB[o * 4 + tid];
    __syncthreads();
    if (tid < 36) {
        int b_ = tid / 9, t = tid - b_ * 9;
        float acc = 0.f;
#pragma unroll
        for (int r = 0; r < 4; r++) acc += Bo[r] * llBinst[(b_ * 4 + r) * 9 + t];
        Bm[b_][t] = fmaxf(acc, 0.f);
    }
    __syncthreads();

    for (int i = tid; i < IN_CH; i += 256) {
        float A0 = llA[i * 4 + 0], A1 = llA[i * 4 + 1];
        float A2 = llA[i * 4 + 2], A3 = llA[i * 4 + 3];
        float w2sum = 0.f;
#pragma unroll
        for (int t = 0; t < 9; t++) {
            float add = fmaxf(A0 * Bm[0][t] + A1 * Bm[1][t] + A2 * Bm[2][t] + A3 * Bm[3][t], 0.f);
            float w = weight[(o * IN_CH + i) * 9 + t] + add;
            g_Wt[((size_t)t * OUT_CH + o) * IN_CH + i] = __float2half_rn(w);
            w2sum += w * w;
        }
        g_W2t[i * OUT_CH + o] = w2sum;
    }
}

// ======================================================================
// Kernel 2: sc[b,i] = CONV_SCALE * (MOD_SCALE * style @ w_fc.T + b_fc)
// ======================================================================
__global__ __launch_bounds__(512) void prep_s_kernel(
    const float* __restrict__ style, const float* __restrict__ modW,
    const float* __restrict__ modB, const float* __restrict__ fcA,
    const float* __restrict__ fcB, const float* __restrict__ fcBias)
{
    const int b  = blockIdx.x >> 3;
    const int i0 = (blockIdx.x & 7) << 6;
    const int tid = threadIdx.x;
    __shared__ float sty[STYLE_DIM];
    sty[tid] = style[b * STYLE_DIM + tid];
    __syncthreads();

    const int warp = tid >> 5, lane = tid & 31;
    for (int ii = warp; ii < 64; ii += 16) {
        const int i = i0 + ii;
        float4 fb = *(const float4*)&fcB[i * 4];
        float acc = 0.f;
        for (int j = lane; j < STYLE_DIM; j += 32) {
            float4 fa = *(const float4*)&fcA[j * 4];
            float wfc = modW[i * STYLE_DIM + j] +
                        (fb.x * fa.x + fb.y * fa.y + fb.z * fa.z + fb.w * fa.w);
            acc += sty[j] * wfc;
        }
#pragma unroll
        for (int off = 16; off; off >>= 1) acc += __shfl_xor_sync(0xFFFFFFFFu, acc, off);
        if (lane == 0) {
            float s = acc * MOD_SCALE + modB[i] + fcBias[i];
            g_sc[b * IN_CH + i] = s * CONV_SCALE;
        }
    }
}

// ======================================================================
// Kernel 3: demod[b,o] = rsqrt(sum_i sc^2 * W2[i][o] + eps)  (exact fp32)
// ======================================================================
__global__ __launch_bounds__(256) void prep_demod_kernel()
{
    const int id = blockIdx.x * 256 + threadIdx.x;
    const int b = id >> 9, o = id & 511;
    const float* scp = &g_sc[b * IN_CH];
    float acc = 0.f;
#pragma unroll 8
    for (int i = 0; i < IN_CH; i++) {
        float sv = scp[i];
        acc = fmaf(sv * sv, g_W2t[i * OUT_CH + o], acc);
    }
    g_demod[b * OUT_CH + o] = rsqrtf(acc + EPSV);
}

// ======================================================================
// Kernel 4: build Xs[b][row][x][i] = fp16( in[b][i][row-1][x] * sc[b,i] )
// rows 0 and 65 are zero padding. grid 528 = (b, row), 256 threads.
// ======================================================================
__global__ __launch_bounds__(256) void prep_xs_kernel(const float* __restrict__ input)
{
    const int b   = blockIdx.x / 66;
    const int row = blockIdx.x - b * 66;
    const int y   = row - 1;
    const bool valid = (unsigned)y < 64u;
    const int tid = threadIdx.x;

    __shared__ float tile[32][65];
    __shared__ float ssc[32];

    for (int i0 = 0; i0 < IN_CH; i0 += 32) {
        __syncthreads();
        if (tid < 32) ssc[tid] = g_sc[b * IN_CH + i0 + tid];
        if (valid) {
#pragma unroll
            for (int p = 0; p < 8; p++) {
                int idx = tid + p * 256;
                int ii = idx >> 6, x = idx & 63;
                tile[ii][x] = input[((size_t)b * IN_CH + i0 + ii) * NPIX + y * 64 + x];
            }
        }
        __syncthreads();
        size_t obase = (((size_t)b * 66 + row) * 64) * IN_CH;
#pragma unroll
        for (int p = 0; p < 4; p++) {
            int idx = tid + p * 256;      // 0..1023
            int x  = idx >> 4;            // 0..63
            int ip = (idx & 15) * 2;      // even i_local
            float s0 = 0.f, s1 = 0.f;
            if (valid) {
                s0 = tile[ip][x]     * ssc[ip];
                s1 = tile[ip + 1][x] * ssc[ip + 1];
            }
            *(__half2*)&g_Xs[obase + (size_t)x * IN_CH + i0 + ip] =
                __floats2half2_rn(s0, s1);
        }
    }
}

// ======================================================================
// Kernel 5: fp16 mma.sync implicit-GEMM conv, occupancy-tuned.
// CTA: M=128 px (2 y-rows) x N=128 o. 8 warps (2 m x 4 n), warp tile 64x32.
// acc[4][4][4] = 64 regs/thread -> 2 CTAs/SM (16 warps) via launch_bounds.
// K loop: 9 taps x 8 chunks of K=64 halves (row = 128B, SW128 swizzle),
// cp.async double-buffered (2 x 32KB).
// grid (32 Mtiles, 4 Ntiles, 8 b) = 1024 CTAs, 256 threads, 64KB dyn smem.
// ======================================================================
#define STAGE_BYTES 32768   // A 16384 + B 16384
#define DSMEM_BYTES (2 * STAGE_BYTES)

__global__ __launch_bounds__(256, 2) void conv_tc_kernel(float* __restrict__ out)
{
    extern __shared__ __align__(16) char dyn[];
    __shared__ float sDm[128];

    const int T  = blockIdx.x;            // M tile: output rows 2T..2T+1
    const int o0 = blockIdx.y << 7;       // N tile base (128 o)
    const int b  = blockIdx.z;
    const int tid  = threadIdx.x;
    const int lane = tid & 31;
    const int wid  = tid >> 5;
    const int wm = wid >> 2;              // 0..1  (m warp: 64 px = y-row wm)
    const int wn = wid & 3;               // 0..3  (n warp: 32 o)
    const uint32_t sbase = s2u(dyn);

    if (tid < 128) sDm[tid] = g_demod[b * OUT_CH + o0 + tid];

    // ---- load-side constants (16B segment = 8 halves; 128B row) ----
    const int g  = tid & 7;               // k-segment 0..7
    const int r0 = tid >> 3;              // base row 0..31; rows r0 + 32j
    const uint32_t dst0 = (uint32_t)(r0 * 128) + (((uint32_t)g * 16) ^ ((uint32_t)(r0 & 7) << 4));

    // ---- compute-side constants ----
    const int rF  = lane & 15;            // fragment row (m for A, n for B)
    const int gh  = lane >> 4;            // k-half (16B)
    const uint32_t maskF = (uint32_t)((rF & 7) << 4);
    const uint32_t offA0 = (uint32_t)((wm * 64 + rF) * 128);
    const uint32_t offB0 = (uint32_t)((wn * 32 + rF) * 128);

    float acc[4][4][4];
#pragma unroll
    for (int mt = 0; mt < 4; mt++)
#pragma unroll
        for (int nt = 0; nt < 4; nt++)
#pragma unroll
            for (int q = 0; q < 4; q++) acc[mt][nt][q] = 0.f;

    const __half* Xb = g_Xs + ((size_t)b * 66) * 64 * IN_CH;

    // chunk loader: it in 0..71 -> (tap = it>>3, i0 = (it&7)*64)
    auto load_chunk = [&](int it, int stage) {
        const int t  = it >> 3;
        const int i0 = (it & 7) << 6;
        const int kh = t / 3;
        const int kw = t - kh * 3;
        const int rowbase = 2 * T + kh;          // padded row of first pixel row
        const uint32_t sA = sbase + stage * STAGE_BYTES;
        const uint32_t sB = sA + 16384;
        // A: 128 rows (pixels) x 64 halves
#pragma unroll
        for (int j = 0; j < 4; j++) {
            int px = r0 + 32 * j;
            int x  = px & 63;
            int xs = x + kw - 1;
            int yp = rowbase + (px >> 6);
            uint32_t ok = ((unsigned)xs < 64u) ? 16u : 0u;
            int xsc = ok ? xs : 0;
            const __half* src = Xb + ((size_t)yp * 64 + xsc) * IN_CH + i0 + g * 8;
            cp16z(sA + dst0 + j * 4096, src, ok);
        }
        // B: 128 rows (o) x 64 halves
        const __half* wsrc = g_Wt + ((size_t)t * OUT_CH + o0) * IN_CH + i0 + g * 8;
#pragma unroll
        for (int j = 0; j < 4; j++) {
            cp16(sB + dst0 + j * 4096, wsrc + (size_t)(r0 + 32 * j) * IN_CH);
        }
        asm volatile("cp.async.commit_group;" ::: "memory");
    };

    load_chunk(0, 0);

#pragma unroll 1
    for (int it = 0; it < 72; it++) {
        const int p = it & 1;
        if (it < 71) {
            load_chunk(it + 1, p ^ 1);
            asm volatile("cp.async.wait_group 1;" ::: "memory");
        } else {
            asm volatile("cp.async.wait_group 0;" ::: "memory");
        }
        __syncthreads();

        const uint32_t aA = sbase + p * STAGE_BYTES;
        const uint32_t aB = aA + 16384;
#pragma unroll
        for (int ks = 0; ks < 4; ks++) {          // 4 k16 groups in K=64
            const uint32_t kcol = ((uint32_t)(ks * 32 + gh * 16)) ^ maskF;
            uint32_t af[4][4];
#pragma unroll
            for (int mt = 0; mt < 4; mt++)
                ldsm4(af[mt], aA + offA0 + mt * 2048 + kcol);
            uint32_t bf[2][4];
#pragma unroll
            for (int np = 0; np < 2; np++)
                ldsm4(bf[np], aB + offB0 + np * 2048 + kcol);
            // bf[np]: {n0-7 klo, n8-15 klo, n0-7 khi, n8-15 khi} for n-group np
#pragma unroll
            for (int mt = 0; mt < 4; mt++) {
#pragma unroll
                for (int nt = 0; nt < 4; nt++) {
                    const int np = nt >> 1, h = nt & 1;
                    mma16(acc[mt][nt], af[mt], bf[np][h], bf[np][h + 2]);
                }
            }
        }
        __syncthreads();
    }

    // ---- epilogue: y = 2T + wm; x = mt*16 + lane/4 (+8); n = wn*32+nt*8+2*(lane&3) (+1)
    const int y  = 2 * T + wm;
    const int xr = lane >> 2;
#pragma unroll
    for (int mt = 0; mt < 4; mt++) {
        const int x0 = mt * 16 + xr;
#pragma unroll
        for (int nt = 0; nt < 4; nt++) {
            const int n0 = wn * 32 + nt * 8 + 2 * (lane & 3);
            const float dm0 = sDm[n0], dm1 = sDm[n0 + 1];
            float* b0p = out + ((size_t)(b * OUT_CH + o0 + n0)) * NPIX + y * 64;
            float* b1p = b0p + NPIX;
            b0p[x0]     = acc[mt][nt][0] * dm0;
            b1p[x0]     = acc[mt][nt][1] * dm1;
            b0p[x0 + 8] = acc[mt][nt][2] * dm0;
            b1p[x0 + 8] = acc[mt][nt][3] * dm1;
        }
    }
}

// ======================================================================
extern "C" void kernel_launch(void* const* d_in, const int* in_sizes, int n_in,
                              void* d_out, int out_size)
{
    const float* input   = (const float*)d_in[0];
    const float* style   = (const float*)d_in[1];
    const float* weight  = (const float*)d_in[2];
    const float* llB     = (const float*)d_in[3];
    const float* llBinst = (const float*)d_in[4];
    const float* llA     = (const float*)d_in[5];
    const float* modW    = (const float*)d_in[6];
    const float* modB    = (const float*)d_in[7];
    const float* fcA     = (const float*)d_in[8];
    const float* fcB     = (const float*)d_in[9];
    const float* fcBias  = (const float*)d_in[10];
    float* out = (float*)d_out;

    cudaFuncSetAttribute(conv_tc_kernel,
                         cudaFuncAttributeMaxDynamicSharedMemorySize, DSMEM_BYTES);

    prep_w5_kernel<<<512, 256>>>(weight, llB, llBinst, llA);
    prep_s_kernel<<<64, 512>>>(style, modW, modB, fcA, fcB, fcBias);
    prep_demod_kernel<<<16, 256>>>();
    prep_xs_kernel<<<528, 256>>>(input);
    conv_tc_kernel<<<dim3(32, 4, 8), 256, DSMEM_BYTES>>>(out);
}